// round 5
// baseline (speedup 1.0000x reference)
#include <cuda_runtime.h>
#include <math.h>

#define TT 32
#define DD 256
#define HH 768
#define GRIDN 128
#define NT 256

#define OFF_HXLAST (TT*128*HH)
#define OFF_PC     (OFF_HXLAST + 128*HH)
#define OFF_STEPS  (OFF_PC + 128)

typedef unsigned long long ull;

// persistent scratch (allocation-free rule)
__device__ float g_hxi[2][128][HH];               // double-buffered hidden state
__device__ float g_pd[8*128*32];                  // partial ponder dots [n][row][cg]
__device__ __align__(16) unsigned g_flags[GRIDN]; // barrier flags (monotonic)

struct SM {
  ull   whh[HH*16];     // [k][16 slots], slot=(pair+2*(k/96))&15, 98304 B
  ull   wih[DD*16];     // [k][16 slots], slot=(pair+2*(k/32))&15, 32768 B
  float hxn[32][26];
  float ahx[32][26];
  float wp[24];
  float ah[128], sc[128], spc[128], coef[128], pc[128];
  int   mask[128];
};

__device__ __forceinline__ ull fma2(ull a, ull b, ull c){
  ull d; asm("fma.rn.f32x2 %0,%1,%2,%3;" : "=l"(d) : "l"(a), "l"(b), "l"(c)); return d;
}
__device__ __forceinline__ ull add2(ull a, ull b){
  ull d; asm("add.rn.f32x2 %0,%1,%2;" : "=l"(d) : "l"(a), "l"(b)); return d;
}
__device__ __forceinline__ ull dup2(float x){
  ull d; unsigned r = __float_as_uint(x);
  asm("mov.b64 %0,{%1,%1};" : "=l"(d) : "r"(r)); return d;
}
__device__ __forceinline__ ull shx64(ull v, int m){
  unsigned lo = (unsigned)v, hi = (unsigned)(v >> 32);
  lo = __shfl_xor_sync(0xffffffffu, lo, m);
  hi = __shfl_xor_sync(0xffffffffu, hi, m);
  return ((ull)hi << 32) | lo;
}

// flag-based grid barrier
__device__ __forceinline__ void gbar(unsigned ep){
  __syncthreads();
  if (threadIdx.x == 0)
    asm volatile("st.release.gpu.global.u32 [%0], %1;"
                 :: "l"(&g_flags[blockIdx.x]), "r"(ep) : "memory");
  if (threadIdx.x < 32){
    const unsigned* fp = g_flags + threadIdx.x*4;
    for(;;){
      unsigned a,b,c,d;
      asm volatile("ld.relaxed.gpu.global.v4.u32 {%0,%1,%2,%3}, [%4];"
                   : "=r"(a),"=r"(b),"=r"(c),"=r"(d) : "l"(fp) : "memory");
      if ((int)(a-ep)>=0 && (int)(b-ep)>=0 && (int)(c-ep)>=0 && (int)(d-ep)>=0) break;
    }
    asm volatile("fence.acq_rel.gpu;" ::: "memory");
  }
  __syncthreads();
}

// warp tile 8 rows x 6 pairs; thread: 4 rows x 3 pairs, K contiguous slice (NJ float4's)
template<int NJ, bool CG>
__device__ __forceinline__ void gemm12(ull (&acc)[12],
    const float* x0, const float* x1, const float* x2, const float* x3,
    const ull* w0, const ull* w1, const ull* w2)
{
  const float4* xp[4];
  xp[0]=(const float4*)x0; xp[1]=(const float4*)x1;
  xp[2]=(const float4*)x2; xp[3]=(const float4*)x3;
  float4 xc[4], xn[4];
  #pragma unroll
  for (int r=0;r<4;r++) xc[r] = CG ? __ldcg(xp[r]) : __ldg(xp[r]);
  #pragma unroll 4
  for (int j=0;j<NJ;++j){
    if (j+1<NJ){
      #pragma unroll
      for (int r=0;r<4;r++) xn[r] = CG ? __ldcg(xp[r]+j+1) : __ldg(xp[r]+j+1);
    }
    #pragma unroll
    for (int jj=0;jj<4;++jj){
      ull wa = *w0, wb = *w1, wc = *w2;
      w0 += 16; w1 += 16; w2 += 16;
      #pragma unroll
      for (int r=0;r<4;r++){
        ull xd = dup2(((const float*)&xc[r])[jj]);
        acc[r*3+0] = fma2(xd, wa, acc[r*3+0]);
        acc[r*3+1] = fma2(xd, wb, acc[r*3+1]);
        acc[r*3+2] = fma2(xd, wc, acc[r*3+2]);
      }
    }
    #pragma unroll
    for (int r=0;r<4;r++) xc[r] = xn[r];
  }
}

__device__ __forceinline__ void reduce12(ull (&acc)[12]){
  #pragma unroll
  for (int p=0;p<12;++p){
    acc[p] = add2(acc[p], shx64(acc[p],1));
    acc[p] = add2(acc[p], shx64(acc[p],2));
    acc[p] = add2(acc[p], shx64(acc[p],4));
  }
}

__global__ void __launch_bounds__(NT, 1)
act_kernel(const float* __restrict__ input, const float* __restrict__ Wih,
           const float* __restrict__ Whh, const float* __restrict__ bih,
           const float* __restrict__ bhh, const float* __restrict__ wpv,
           const float* __restrict__ bpv, float* __restrict__ out)
{
  extern __shared__ unsigned char smraw[];
  SM& s = *reinterpret_cast<SM*>(smraw);
  const int tid = threadIdx.x, blk = blockIdx.x;
  const int rg = blk >> 5, cg = blk & 31;
  const int row0 = rg*32, col0 = cg*24;
  const int lane = tid & 31, warp = tid >> 5;
  const int kl = lane & 7, u = lane >> 3;
  const int phh = warp >> 2;             // pair half (0/1)
  const int wrow = (warp & 3) * 8;       // warp row base
  const int u_row = u & 1, u_tri = u >> 1;
  const int r0t = wrow + u_row*4;        // thread's 4 local rows start
  const int p0  = phh*6 + u_tri*3;       // block-local pair base (0,3,6,9)

  // weight slot pointers offsets (rotation 2*kl, fixed per thread)
  const int off0 = (p0 + 0 + 2*kl) & 15;
  const int off1 = (p0 + 1 + 2*kl) & 15;
  const int off2 = (p0 + 2 + 2*kl) & 15;

  // ---- one-time: stage weights with slot rotation ----
  for (int idx = tid; idx < 24*HH; idx += NT){
    int c = idx / HH, k = idx - c*HH;
    int slot = ((c >> 1) + 2*(k/96)) & 15;
    ((float*)&s.whh[(size_t)k*16 + slot])[c & 1] = Whh[(size_t)(col0+c)*HH + k];
  }
  for (int idx = tid; idx < 24*DD; idx += NT){
    int c = idx / DD, k = idx - c*DD;
    int slot = ((c >> 1) + 2*(k/32)) & 15;
    ((float*)&s.wih[(size_t)k*16 + slot])[c & 1] = Wih[(size_t)(col0+c)*(DD+1) + k];
  }
  if (tid < 24) s.wp[tid] = wpv[col0+tid];
  if (tid < 128) s.pc[tid] = 0.f;
  for (int e = tid; e < 32*24; e += NT){
    int r2 = e/24, c2 = e - r2*24;
    g_hxi[0][row0+r2][col0+c2] = 0.f;
  }

  // epilogue-thread registers: output coords, flag weights, biases
  int rrA=0, ccA=0, rrB=0, ccB=0;
  float flwA0=0,flwA1=0,flwB0=0,flwB1=0;
  float bsA0=0,bsA1=0,bsB0=0,bsB1=0;   // biases now, base later
  if (kl < 6){
    int idxA = kl*2, idxB = kl*2 + 1;
    int rA = idxA/3, mA = idxA - rA*3;
    int rB = idxB/3, mB = idxB - rB*3;
    rrA = r0t + rA; ccA = (p0 + mA)*2;
    rrB = r0t + rB; ccB = (p0 + mB)*2;
    flwA0 = Wih[(size_t)(col0+ccA  )*(DD+1) + DD];
    flwA1 = Wih[(size_t)(col0+ccA+1)*(DD+1) + DD];
    flwB0 = Wih[(size_t)(col0+ccB  )*(DD+1) + DD];
    flwB1 = Wih[(size_t)(col0+ccB+1)*(DD+1) + DD];
    bsA0 = bih[col0+ccA  ] + bhh[col0+ccA  ];
    bsA1 = bih[col0+ccA+1] + bhh[col0+ccA+1];
    bsB0 = bih[col0+ccB  ] + bhh[col0+ccB  ];
    bsB1 = bih[col0+ccB+1] + bhh[col0+ccB+1];
  }
  const float bp0 = bpv[0];
  int rb = 0;
  unsigned ep = g_flags[blk];
  gbar(++ep);

  for (int t = 0; t < TT; ++t){
    if (tid < 128){ s.ah[tid]=0.f; s.sc[tid]=0.f; s.spc[tid]=0.f; s.mask[tid]=1; }
    for (int e = tid; e < 32*24; e += NT){ int r2=e/24, c2=e-r2*24; s.ahx[r2][c2]=0.f; }

    // ---- base = x_t @ W_ih^T + biases (register-resident per epilogue thread) ----
    float baseA0=0, baseA1=0, baseB0=0, baseB1=0;
    {
      ull acc[12] = {0,0,0,0,0,0,0,0,0,0,0,0};
      const float* xb = input + ((size_t)t*128 + row0 + r0t)*DD + kl*32;
      gemm12<8,false>(acc, xb, xb+DD, xb+2*DD, xb+3*DD,
                      s.wih + (size_t)(kl*32)*16 + off0,
                      s.wih + (size_t)(kl*32)*16 + off1,
                      s.wih + (size_t)(kl*32)*16 + off2);
      reduce12(acc);
      if (kl < 6){
        int idxA = kl*2, idxB = kl*2 + 1;
        float2 fA = *(float2*)&acc[idxA];
        float2 fB = *(float2*)&acc[idxB];
        baseA0 = fA.x + bsA0; baseA1 = fA.y + bsA1;
        baseB0 = fB.x + bsB0; baseB1 = fB.y + bsB1;
      }
    }
    __syncthreads();

    // ---- ponder loop ----
    for (int n = 0; n < 8; ++n){
      ull acc[12] = {0,0,0,0,0,0,0,0,0,0,0,0};
      const float* hb = &g_hxi[rb][row0 + r0t][0] + kl*96;
      gemm12<24,true>(acc, hb, hb+HH, hb+2*HH, hb+3*HH,
                      s.whh + (size_t)(kl*96)*16 + off0,
                      s.whh + (size_t)(kl*96)*16 + off1,
                      s.whh + (size_t)(kl*96)*16 + off2);
      reduce12(acc);

      const float fl = (n == 0) ? 0.f : 1.f;
      if (kl < 6){
        int idxA = kl*2, idxB = kl*2 + 1;
        float2 fA = *(float2*)&acc[idxA];
        float2 fB = *(float2*)&acc[idxB];
        float hA0 = tanhf(fA.x + baseA0 + fl*flwA0);
        float hA1 = tanhf(fA.y + baseA1 + fl*flwA1);
        float hB0 = tanhf(fB.x + baseB0 + fl*flwB0);
        float hB1 = tanhf(fB.y + baseB1 + fl*flwB1);
        s.hxn[rrA][ccA] = hA0; s.hxn[rrA][ccA+1] = hA1;
        s.hxn[rrB][ccB] = hB0; s.hxn[rrB][ccB+1] = hB1;
        int grA = row0 + rrA, gcA = col0 + ccA;
        int grB = row0 + rrB, gcB = col0 + ccB;
        float2 oA, oB;
        if (s.mask[grA]) oA = make_float2(hA0,hA1);
        else             oA = __ldcg((const float2*)&g_hxi[rb][grA][gcA]);
        if (s.mask[grB]) oB = make_float2(hB0,hB1);
        else             oB = __ldcg((const float2*)&g_hxi[rb][grB][gcB]);
        *(float2*)&g_hxi[rb^1][grA][gcA] = oA;
        *(float2*)&g_hxi[rb^1][grB][gcB] = oB;
      }
      __syncthreads();
      if (tid < 32){
        float pd = 0.f;
        #pragma unroll
        for (int c = 0; c < 24; c++) pd = fmaf(s.hxn[tid][c], s.wp[c], pd);
        g_pd[(size_t)(n*128 + row0 + tid)*32 + cg] = pd;
      }
      gbar(++ep);

      // redundant identical scalar update (fixed order => identical everywhere)
      int nm = 0;
      if (tid < 128){
        const float4* pr4 = (const float4*)&g_pd[(size_t)(n*128 + tid)*32];
        float sum = 0.f;
        #pragma unroll
        for (int q = 0; q < 8; q++){
          float4 v4 = __ldcg(pr4 + q);
          sum += v4.x; sum += v4.y; sum += v4.z; sum += v4.w;
        }
        float h = 1.f/(1.f + expf(-(sum + bp0)));
        int   m  = s.mask[tid];
        float mf = m ? 1.f : 0.f;
        if (m) s.spc[tid] = -s.ah[tid];
        float ah2 = s.ah[tid] + mf*h;
        float p2  = h - fmaxf(ah2 - 1.f, 0.f);
        s.coef[tid] = mf*(1.f + p2);
        s.sc[tid]  += mf;
        s.ah[tid]   = ah2;
        int m2 = (ah2 < 0.99f);
        s.mask[tid] = m2;
        nm = m2;
      }
      int nlive = __syncthreads_or(nm);
      for (int e = tid; e < 32*24; e += NT){
        int r2 = e/24, c2 = e - r2*24;
        s.ahx[r2][c2] = fmaf(s.coef[row0+r2], s.hxn[r2][c2], s.ahx[r2][c2]);
      }
      __syncthreads();
      rb ^= 1;
      if (!nlive) break;
    }

    // ---- end of step: outputs + carry ----
    for (int e = tid; e < 32*24; e += NT){
      int r2 = e/24, c2 = e - r2*24;
      int gr2 = row0 + r2, gc2 = col0 + c2;
      float v = s.ahx[r2][c2] / s.sc[gr2];
      out[(size_t)(t*128 + gr2)*HH + gc2] = v;
      if (t == TT-1) out[OFF_HXLAST + (size_t)gr2*HH + gc2] = v;
      g_hxi[rb][gr2][gc2] = v;
    }
    if (blk == 0 && tid < 128){
      s.pc[tid] += s.spc[tid];
      out[OFF_STEPS + t*128 + tid] = s.sc[tid];
    }
    gbar(++ep);
  }

  if (blk == 0 && tid < 128) out[OFF_PC + tid] = s.pc[tid];
}

extern "C" void kernel_launch(void* const* d_in, const int* in_sizes, int n_in,
                              void* d_out, int out_size)
{
  const float* input = (const float*)d_in[0];
  const float* Wih   = (const float*)d_in[1];
  const float* Whh   = (const float*)d_in[2];
  const float* bih   = (const float*)d_in[3];
  const float* bhh   = (const float*)d_in[4];
  const float* wpv   = (const float*)d_in[5];
  const float* bpv   = (const float*)d_in[6];
  (void)in_sizes; (void)n_in; (void)out_size;

  cudaFuncSetAttribute(act_kernel, cudaFuncAttributeMaxDynamicSharedMemorySize, (int)sizeof(SM));
  act_kernel<<<GRIDN, NT, sizeof(SM)>>>(input, Wih, Whh, bih, bhh, wpv, bpv, (float*)d_out);
}

// round 6
// speedup vs baseline: 1.0614x; 1.0614x over previous
#include <cuda_runtime.h>
#include <math.h>

#define TT 32
#define DD 256
#define HH 768
#define GRIDN 128
#define NT 256

#define OFF_HXLAST (TT*128*HH)
#define OFF_PC     (OFF_HXLAST + 128*HH)
#define OFF_STEPS  (OFF_PC + 128)

typedef unsigned long long ull;

// persistent scratch (allocation-free rule)
__device__ float g_hxi[2][128][HH];               // double-buffered hidden state
__device__ float g_pd[8*128*32];                  // partial ponder dots [n][row][cg]
__device__ __align__(16) unsigned g_flags[GRIDN]; // barrier flags (monotonic)

struct SM {
  ull   whh[HH*16];     // [k][16 slots], slot=(pair+2*(k/96))&15, 98304 B
  ull   wih[DD*16];     // [k][16 slots], slot=(pair+2*(k/32))&15, 32768 B
  float hxn[32][26];
  float ahx[32][26];
  float wp[24];
  float ah[128], sc[128], spc[128], coef[128], pc[128];
  int   mask[128];
};

__device__ __forceinline__ ull fma2(ull a, ull b, ull c){
  ull d; asm("fma.rn.f32x2 %0,%1,%2,%3;" : "=l"(d) : "l"(a), "l"(b), "l"(c)); return d;
}
__device__ __forceinline__ ull add2(ull a, ull b){
  ull d; asm("add.rn.f32x2 %0,%1,%2;" : "=l"(d) : "l"(a), "l"(b)); return d;
}
__device__ __forceinline__ ull dup2(float x){
  ull d; unsigned r = __float_as_uint(x);
  asm("mov.b64 %0,{%1,%1};" : "=l"(d) : "r"(r)); return d;
}
__device__ __forceinline__ ull shx64(ull v, int m){
  unsigned lo = (unsigned)v, hi = (unsigned)(v >> 32);
  lo = __shfl_xor_sync(0xffffffffu, lo, m);
  hi = __shfl_xor_sync(0xffffffffu, hi, m);
  return ((ull)hi << 32) | lo;
}

// flag-based grid barrier
__device__ __forceinline__ void gbar(unsigned ep){
  __syncthreads();
  if (threadIdx.x == 0)
    asm volatile("st.release.gpu.global.u32 [%0], %1;"
                 :: "l"(&g_flags[blockIdx.x]), "r"(ep) : "memory");
  if (threadIdx.x < 32){
    const unsigned* fp = g_flags + threadIdx.x*4;
    for(;;){
      unsigned a,b,c,d;
      asm volatile("ld.relaxed.gpu.global.v4.u32 {%0,%1,%2,%3}, [%4];"
                   : "=r"(a),"=r"(b),"=r"(c),"=r"(d) : "l"(fp) : "memory");
      if ((int)(a-ep)>=0 && (int)(b-ep)>=0 && (int)(c-ep)>=0 && (int)(d-ep)>=0) break;
    }
    asm volatile("fence.acq_rel.gpu;" ::: "memory");
  }
  __syncthreads();
}

// warp tile 8 rows x 6 pairs; thread: 4 rows x 3 pairs, K contiguous slice (NJ float4's)
// depth-3 software-pipelined x prefetch: 12 LDG.128 in flight per thread.
template<int NJ, bool CG>
__device__ __forceinline__ void gemm12(ull (&acc)[12],
    const float* x0, const float* x1, const float* x2, const float* x3,
    const ull* w0, const ull* w1, const ull* w2)
{
  const float4* xp[4];
  xp[0]=(const float4*)x0; xp[1]=(const float4*)x1;
  xp[2]=(const float4*)x2; xp[3]=(const float4*)x3;
  float4 q0[4], q1[4], q2[4], qn[4];
  #pragma unroll
  for (int r=0;r<4;r++){
    q0[r] = CG ? __ldcg(xp[r]  ) : __ldg(xp[r]  );
    q1[r] = CG ? __ldcg(xp[r]+1) : __ldg(xp[r]+1);
    q2[r] = CG ? __ldcg(xp[r]+2) : __ldg(xp[r]+2);
  }
  #pragma unroll 6
  for (int j=0;j<NJ;++j){
    if (j+3<NJ){
      #pragma unroll
      for (int r=0;r<4;r++) qn[r] = CG ? __ldcg(xp[r]+j+3) : __ldg(xp[r]+j+3);
    }
    #pragma unroll
    for (int jj=0;jj<4;++jj){
      ull wa = *w0, wb = *w1, wc = *w2;
      w0 += 16; w1 += 16; w2 += 16;
      #pragma unroll
      for (int r=0;r<4;r++){
        ull xd = dup2(((const float*)&q0[r])[jj]);
        acc[r*3+0] = fma2(xd, wa, acc[r*3+0]);
        acc[r*3+1] = fma2(xd, wb, acc[r*3+1]);
        acc[r*3+2] = fma2(xd, wc, acc[r*3+2]);
      }
    }
    #pragma unroll
    for (int r=0;r<4;r++){ q0[r]=q1[r]; q1[r]=q2[r]; q2[r]=qn[r]; }
  }
}

__device__ __forceinline__ void reduce12(ull (&acc)[12]){
  #pragma unroll
  for (int p=0;p<12;++p){
    acc[p] = add2(acc[p], shx64(acc[p],1));
    acc[p] = add2(acc[p], shx64(acc[p],2));
    acc[p] = add2(acc[p], shx64(acc[p],4));
  }
}

__global__ void __launch_bounds__(NT, 1)
act_kernel(const float* __restrict__ input, const float* __restrict__ Wih,
           const float* __restrict__ Whh, const float* __restrict__ bih,
           const float* __restrict__ bhh, const float* __restrict__ wpv,
           const float* __restrict__ bpv, float* __restrict__ out)
{
  extern __shared__ unsigned char smraw[];
  SM& s = *reinterpret_cast<SM*>(smraw);
  const int tid = threadIdx.x, blk = blockIdx.x;
  const int rg = blk >> 5, cg = blk & 31;
  const int row0 = rg*32, col0 = cg*24;
  const int lane = tid & 31, warp = tid >> 5;
  const int kl = lane & 7, u = lane >> 3;
  const int phh = warp >> 2;             // pair half (0/1)
  const int wrow = (warp & 3) * 8;       // warp row base
  const int u_row = u & 1, u_tri = u >> 1;
  const int r0t = wrow + u_row*4;        // thread's 4 local rows start
  const int p0  = phh*6 + u_tri*3;       // block-local pair base (0,3,6,9)

  // weight slot offsets (rotation 2*kl, fixed per thread)
  const int off0 = (p0 + 0 + 2*kl) & 15;
  const int off1 = (p0 + 1 + 2*kl) & 15;
  const int off2 = (p0 + 2 + 2*kl) & 15;

  // ---- one-time: stage weights with slot rotation ----
  for (int idx = tid; idx < 24*HH; idx += NT){
    int c = idx / HH, k = idx - c*HH;
    int slot = ((c >> 1) + 2*(k/96)) & 15;
    ((float*)&s.whh[(size_t)k*16 + slot])[c & 1] = Whh[(size_t)(col0+c)*HH + k];
  }
  for (int idx = tid; idx < 24*DD; idx += NT){
    int c = idx / DD, k = idx - c*DD;
    int slot = ((c >> 1) + 2*(k/32)) & 15;
    ((float*)&s.wih[(size_t)k*16 + slot])[c & 1] = Wih[(size_t)(col0+c)*(DD+1) + k];
  }
  if (tid < 24) s.wp[tid] = wpv[col0+tid];
  if (tid < 128) s.pc[tid] = 0.f;
  for (int e = tid; e < 32*24; e += NT){
    int r2 = e/24, c2 = e - r2*24;
    g_hxi[0][row0+r2][col0+c2] = 0.f;
  }

  // epilogue-thread registers: output coords, flag weights, biases
  int rrA=0, ccA=0, rrB=0, ccB=0;
  float flwA0=0,flwA1=0,flwB0=0,flwB1=0;
  float bsA0=0,bsA1=0,bsB0=0,bsB1=0;
  if (kl < 6){
    int idxA = kl*2, idxB = kl*2 + 1;
    int rA = idxA/3, mA = idxA - rA*3;
    int rB = idxB/3, mB = idxB - rB*3;
    rrA = r0t + rA; ccA = (p0 + mA)*2;
    rrB = r0t + rB; ccB = (p0 + mB)*2;
    flwA0 = Wih[(size_t)(col0+ccA  )*(DD+1) + DD];
    flwA1 = Wih[(size_t)(col0+ccA+1)*(DD+1) + DD];
    flwB0 = Wih[(size_t)(col0+ccB  )*(DD+1) + DD];
    flwB1 = Wih[(size_t)(col0+ccB+1)*(DD+1) + DD];
    bsA0 = bih[col0+ccA  ] + bhh[col0+ccA  ];
    bsA1 = bih[col0+ccA+1] + bhh[col0+ccA+1];
    bsB0 = bih[col0+ccB  ] + bhh[col0+ccB  ];
    bsB1 = bih[col0+ccB+1] + bhh[col0+ccB+1];
  }
  const float bp0 = bpv[0];
  int rb = 0;
  unsigned ep = g_flags[blk];
  gbar(++ep);

  for (int t = 0; t < TT; ++t){
    if (tid < 128){ s.ah[tid]=0.f; s.sc[tid]=0.f; s.spc[tid]=0.f; s.mask[tid]=1; }
    for (int e = tid; e < 32*24; e += NT){ int r2=e/24, c2=e-r2*24; s.ahx[r2][c2]=0.f; }

    // ---- base = x_t @ W_ih^T + biases (register-resident) ----
    float baseA0=0, baseA1=0, baseB0=0, baseB1=0;
    {
      ull acc[12] = {0,0,0,0,0,0,0,0,0,0,0,0};
      const float* xb = input + ((size_t)t*128 + row0 + r0t)*DD + kl*32;
      gemm12<8,false>(acc, xb, xb+DD, xb+2*DD, xb+3*DD,
                      s.wih + (size_t)(kl*32)*16 + off0,
                      s.wih + (size_t)(kl*32)*16 + off1,
                      s.wih + (size_t)(kl*32)*16 + off2);
      reduce12(acc);
      if (kl < 6){
        int idxA = kl*2, idxB = kl*2 + 1;
        float2 fA = *(float2*)&acc[idxA];
        float2 fB = *(float2*)&acc[idxB];
        baseA0 = fA.x + bsA0; baseA1 = fA.y + bsA1;
        baseB0 = fB.x + bsB0; baseB1 = fB.y + bsB1;
      }
    }
    __syncthreads();

    // ---- ponder loop ----
    for (int n = 0; n < 8; ++n){
      ull acc[12] = {0,0,0,0,0,0,0,0,0,0,0,0};
      const float* hb = &g_hxi[rb][row0 + r0t][0] + kl*96;
      gemm12<24,true>(acc, hb, hb+HH, hb+2*HH, hb+3*HH,
                      s.whh + (size_t)(kl*96)*16 + off0,
                      s.whh + (size_t)(kl*96)*16 + off1,
                      s.whh + (size_t)(kl*96)*16 + off2);
      reduce12(acc);

      const float fl = (n == 0) ? 0.f : 1.f;
      if (kl < 6){
        int idxA = kl*2, idxB = kl*2 + 1;
        float2 fA = *(float2*)&acc[idxA];
        float2 fB = *(float2*)&acc[idxB];
        float hA0 = tanhf(fA.x + baseA0 + fl*flwA0);
        float hA1 = tanhf(fA.y + baseA1 + fl*flwA1);
        float hB0 = tanhf(fB.x + baseB0 + fl*flwB0);
        float hB1 = tanhf(fB.y + baseB1 + fl*flwB1);
        s.hxn[rrA][ccA] = hA0; s.hxn[rrA][ccA+1] = hA1;
        s.hxn[rrB][ccB] = hB0; s.hxn[rrB][ccB+1] = hB1;
        int grA = row0 + rrA, gcA = col0 + ccA;
        int grB = row0 + rrB, gcB = col0 + ccB;
        float2 oA, oB;
        if (s.mask[grA]) oA = make_float2(hA0,hA1);
        else             oA = __ldcg((const float2*)&g_hxi[rb][grA][gcA]);
        if (s.mask[grB]) oB = make_float2(hB0,hB1);
        else             oB = __ldcg((const float2*)&g_hxi[rb][grB][gcB]);
        *(float2*)&g_hxi[rb^1][grA][gcA] = oA;
        *(float2*)&g_hxi[rb^1][grB][gcB] = oB;
      }
      __syncthreads();
      if (tid < 32){
        float pd = 0.f;
        #pragma unroll
        for (int c = 0; c < 24; c++) pd = fmaf(s.hxn[tid][c], s.wp[c], pd);
        g_pd[(size_t)(n*128 + row0 + tid)*32 + cg] = pd;
      }
      gbar(++ep);

      // redundant identical scalar update (fixed order => identical everywhere)
      int nm = 0;
      if (tid < 128){
        const float4* pr4 = (const float4*)&g_pd[(size_t)(n*128 + tid)*32];
        float sum = 0.f;
        #pragma unroll
        for (int q = 0; q < 8; q++){
          float4 v4 = __ldcg(pr4 + q);
          sum += v4.x; sum += v4.y; sum += v4.z; sum += v4.w;
        }
        float h = 1.f/(1.f + expf(-(sum + bp0)));
        int   m  = s.mask[tid];
        float mf = m ? 1.f : 0.f;
        if (m) s.spc[tid] = -s.ah[tid];
        float ah2 = s.ah[tid] + mf*h;
        float p2  = h - fmaxf(ah2 - 1.f, 0.f);
        s.coef[tid] = mf*(1.f + p2);
        s.sc[tid]  += mf;
        s.ah[tid]   = ah2;
        int m2 = (ah2 < 0.99f);
        s.mask[tid] = m2;
        nm = m2;
      }
      int nlive = __syncthreads_or(nm);
      for (int e = tid; e < 32*24; e += NT){
        int r2 = e/24, c2 = e - r2*24;
        s.ahx[r2][c2] = fmaf(s.coef[row0+r2], s.hxn[r2][c2], s.ahx[r2][c2]);
      }
      __syncthreads();
      rb ^= 1;
      if (!nlive) break;
    }

    // ---- end of step: outputs + carry ----
    for (int e = tid; e < 32*24; e += NT){
      int r2 = e/24, c2 = e - r2*24;
      int gr2 = row0 + r2, gc2 = col0 + c2;
      float v = s.ahx[r2][c2] / s.sc[gr2];
      out[(size_t)(t*128 + gr2)*HH + gc2] = v;
      if (t == TT-1) out[OFF_HXLAST + (size_t)gr2*HH + gc2] = v;
      g_hxi[rb][gr2][gc2] = v;
    }
    if (blk == 0 && tid < 128){
      s.pc[tid] += s.spc[tid];
      out[OFF_STEPS + t*128 + tid] = s.sc[tid];
    }
    gbar(++ep);
  }

  if (blk == 0 && tid < 128) out[OFF_PC + tid] = s.pc[tid];
}

extern "C" void kernel_launch(void* const* d_in, const int* in_sizes, int n_in,
                              void* d_out, int out_size)
{
  const float* input = (const float*)d_in[0];
  const float* Wih   = (const float*)d_in[1];
  const float* Whh   = (const float*)d_in[2];
  const float* bih   = (const float*)d_in[3];
  const float* bhh   = (const float*)d_in[4];
  const float* wpv   = (const float*)d_in[5];
  const float* bpv   = (const float*)d_in[6];
  (void)in_sizes; (void)n_in; (void)out_size;

  cudaFuncSetAttribute(act_kernel, cudaFuncAttributeMaxDynamicSharedMemorySize, (int)sizeof(SM));
  act_kernel<<<GRIDN, NT, sizeof(SM)>>>(input, Wih, Whh, bih, bhh, wpv, bpv, (float*)d_out);
}